// round 9
// baseline (speedup 1.0000x reference)
#include <cuda_runtime.h>
#include <cuda_bf16.h>
#include <cstdint>

// NonLocalBlock: B=4, C=64, Ci=32, H=W=64, N=4096
// z = supp + W( softmax_n(theta(supp)^T phi(ref)) @ g(ref) ) + wb
//
//  prep : projections (fp32 math, bf16 out); theta pre-scaled by log2(e); MLP16
//  pass1: partial colsum[m] = sum_n 2^f' per n-half (512 blocks, 16 iters)
//  pass2: recompute S on an m-half, P = 2^f' * colinv, bf16 partial x1 (512 blocks)
//  fin  : sum 4 bf16 x1 quarters (1 uint4/thread/quarter) + fused conv epilogue
// GEMMs via mma.sync.m16n8k16 bf16/fp32. No max-subtraction needed (f ~ N(0,1),
// |f| <~ 6 over 67M samples; softmax shift-invariant).

#define B_ 4
#define C_ 64
#define CI 32
#define N_ 4096
#define LOG2E 1.4426950408889634f

typedef __nv_bfloat16 bf16;

__device__ __align__(16) bf16 g_theta[B_ * N_ * CI];    // [b][n][ci] (x log2e)
__device__ __align__(16) bf16 g_phi[B_ * N_ * CI];      // [b][m][ci]
__device__ __align__(16) bf16 g_gy[B_ * CI * N_];       // [b][ci][m]
__device__ __align__(16) float g_colpart[2][B_ * N_];   // [half][b][m]
__device__ __align__(16) bf16 g_x1p[B_ * 4 * N_ * CI];  // [b][quarter][n][ci]

__device__ __forceinline__ uint32_t pack_bf2(float x, float y) {
    __nv_bfloat162 h = __float22bfloat162_rn(make_float2(x, y));
    return *reinterpret_cast<uint32_t*>(&h);
}

__device__ __forceinline__ float ex2f(float x) {
    float y;
    asm("ex2.approx.ftz.f32 %0, %1;" : "=f"(y) : "f"(x));
    return y;
}

__device__ __forceinline__ void mma16816(float* c, const uint32_t* a, const uint32_t* b) {
    asm volatile(
        "mma.sync.aligned.m16n8k16.row.col.f32.bf16.bf16.f32 "
        "{%0,%1,%2,%3}, {%4,%5,%6,%7}, {%8,%9}, {%0,%1,%2,%3};\n"
        : "+f"(c[0]), "+f"(c[1]), "+f"(c[2]), "+f"(c[3])
        : "r"(a[0]), "r"(a[1]), "r"(a[2]), "r"(a[3]), "r"(b[0]), "r"(b[1]));
}

__device__ __forceinline__ void cp16(void* dst, const void* src) {
    uint32_t s = (uint32_t)__cvta_generic_to_shared(dst);
    asm volatile("cp.async.cg.shared.global [%0], [%1], 16;\n" :: "r"(s), "l"(src));
}
#define CP_COMMIT asm volatile("cp.async.commit_group;\n")
#define CP_WAIT0  asm volatile("cp.async.wait_group 0;\n")

// ---------------------------------------------------------------------------
// prep: grid (N/256, B, 6), block 256. z = proj*2 + half; 16 outputs/thread.
// c-loop batched x16 for MLP. theta scaled by log2(e).
// ---------------------------------------------------------------------------
__global__ __launch_bounds__(256) void prep_kernel(
    const float* __restrict__ supp, const float* __restrict__ ref,
    const float* __restrict__ tw, const float* __restrict__ tb,
    const float* __restrict__ pw, const float* __restrict__ pb,
    const float* __restrict__ gw, const float* __restrict__ gb) {
    __shared__ float sw[16 * C_];
    __shared__ float sb[16];
    int tid = threadIdx.x;
    int z = blockIdx.z;
    int proj = z >> 1, half = z & 1;
    const float* wsel = (proj == 0) ? tw : (proj == 1) ? pw : gw;
    const float* bsel = (proj == 0) ? tb : (proj == 1) ? pb : gb;
    const float* xsel = (proj == 0) ? supp : ref;
    for (int i = tid; i < 16 * C_; i += 256) sw[i] = wsel[half * 16 * C_ + i];
    if (tid < 16) sb[tid] = bsel[half * 16 + tid];
    __syncthreads();

    int b = blockIdx.y;
    int n = blockIdx.x * 256 + tid;
    const float* xp = xsel + (size_t)b * C_ * N_ + n;

    float acc[16];
#pragma unroll
    for (int i = 0; i < 16; i++) acc[i] = sb[i];
#pragma unroll
    for (int c0 = 0; c0 < C_; c0 += 16) {
        float v[16];
#pragma unroll
        for (int k = 0; k < 16; k++) v[k] = xp[(size_t)(c0 + k) * N_];
#pragma unroll
        for (int k = 0; k < 16; k++)
#pragma unroll
            for (int i = 0; i < 16; i++) acc[i] += sw[i * C_ + c0 + k] * v[k];
    }

    if (proj == 0) {
#pragma unroll
        for (int i = 0; i < 16; i++) acc[i] *= LOG2E;
        uint32_t* dst = (uint32_t*)(g_theta + (size_t)b * N_ * CI) + (size_t)n * 16 + half * 8;
#pragma unroll
        for (int i = 0; i < 8; i++) dst[i] = pack_bf2(acc[2 * i], acc[2 * i + 1]);
    } else if (proj == 1) {
        uint32_t* dst = (uint32_t*)(g_phi + (size_t)b * N_ * CI) + (size_t)n * 16 + half * 8;
#pragma unroll
        for (int i = 0; i < 8; i++) dst[i] = pack_bf2(acc[2 * i], acc[2 * i + 1]);
    } else {
#pragma unroll
        for (int i = 0; i < 16; i++)
            g_gy[(size_t)b * CI * N_ + (size_t)(half * 16 + i) * N_ + n] = __float2bfloat16(acc[i]);
    }
}

// ---------------------------------------------------------------------------
// pass1: grid (N/64 m-tiles, B, 2 n-halves), block 256 (8 warps x 16 rows).
// Partial colsum over this block's 2048-row n-half; single barrier per iter.
// ---------------------------------------------------------------------------
__global__ __launch_bounds__(256) void pass1_kernel() {
    __shared__ __align__(16) bf16 At[2][128 * 40];
    __shared__ float cs[64];
    int tid = threadIdx.x;
    int lane = tid & 31, w = tid >> 5;
    int g = lane >> 2, tg = lane & 3;
    int b = blockIdx.y;
    int half = blockIdx.z;
    int m0 = blockIdx.x * 64;
    const bf16* thB = g_theta + (size_t)b * N_ * CI + (size_t)half * 2048 * CI;
    const bf16* phB = g_phi + (size_t)b * N_ * CI;

    uint32_t bfr[8][2][2];
#pragma unroll
    for (int j = 0; j < 8; j++)
#pragma unroll
        for (int kk = 0; kk < 2; kk++) {
            const bf16* p = phB + (size_t)(m0 + j * 8 + g) * CI + kk * 16 + tg * 2;
            bfr[j][kk][0] = *(const uint32_t*)p;
            bfr[j][kk][1] = *(const uint32_t*)(p + 8);
        }
    float part[16];
#pragma unroll
    for (int i = 0; i < 16; i++) part[i] = 0.f;
    if (tid < 64) cs[tid] = 0.f;

    {   // prologue: theta tile 0
        int i0 = tid, i1 = tid + 256;
        cp16(&At[0][(i0 >> 2) * 40 + (i0 & 3) * 8], thB + (size_t)(i0 >> 2) * CI + (i0 & 3) * 8);
        cp16(&At[0][(i1 >> 2) * 40 + (i1 & 3) * 8], thB + (size_t)(i1 >> 2) * CI + (i1 & 3) * 8);
        CP_COMMIT;
    }
    for (int nt = 0; nt < 16; ++nt) {
        CP_WAIT0;
        __syncthreads();
        if (nt + 1 < 16) {
            const bf16* s = thB + (size_t)(nt + 1) * 128 * CI;
            bf16* d = At[(nt + 1) & 1];
            int i0 = tid, i1 = tid + 256;
            cp16(&d[(i0 >> 2) * 40 + (i0 & 3) * 8], s + (size_t)(i0 >> 2) * CI + (i0 & 3) * 8);
            cp16(&d[(i1 >> 2) * 40 + (i1 & 3) * 8], s + (size_t)(i1 >> 2) * CI + (i1 & 3) * 8);
            CP_COMMIT;
        }
        uint32_t a[2][4];
        const bf16* Ar = At[nt & 1] + (w * 16) * 40;
#pragma unroll
        for (int kk = 0; kk < 2; kk++) {
            a[kk][0] = *(const uint32_t*)(Ar + g * 40 + kk * 16 + tg * 2);
            a[kk][1] = *(const uint32_t*)(Ar + (g + 8) * 40 + kk * 16 + tg * 2);
            a[kk][2] = *(const uint32_t*)(Ar + g * 40 + kk * 16 + tg * 2 + 8);
            a[kk][3] = *(const uint32_t*)(Ar + (g + 8) * 40 + kk * 16 + tg * 2 + 8);
        }
#pragma unroll
        for (int j = 0; j < 8; j++) {
            float c[4] = {0.f, 0.f, 0.f, 0.f};
            mma16816(c, a[0], bfr[j][0]);
            mma16816(c, a[1], bfr[j][1]);
            part[j * 2] += ex2f(c[0]) + ex2f(c[2]);
            part[j * 2 + 1] += ex2f(c[1]) + ex2f(c[3]);
        }
    }
#pragma unroll
    for (int off = 4; off <= 16; off <<= 1)
#pragma unroll
        for (int i = 0; i < 16; i++) part[i] += __shfl_xor_sync(0xffffffffu, part[i], off);
    __syncthreads();
    if (g == 0) {
#pragma unroll
        for (int j = 0; j < 8; j++) {
            atomicAdd(&cs[j * 8 + tg * 2], part[j * 2]);
            atomicAdd(&cs[j * 8 + tg * 2 + 1], part[j * 2 + 1]);
        }
    }
    __syncthreads();
    if (tid < 64) g_colpart[half][(size_t)b * N_ + m0 + tid] = cs[tid];
}

// ---------------------------------------------------------------------------
// pass2: grid (N/64 n-tiles, B, 2 m-halves), block 256 (8 warps).
// Warp w: row-group wq=w&3 (rows n0+wq*16), mh=w>>2 (32-wide slice of 64-tile).
// Recomputes S on its 2048-wide m-half; P=2^f'*colinv; bf16 partial x1 out.
// ---------------------------------------------------------------------------
__global__ __launch_bounds__(256) void pass2_kernel() {
    __shared__ __align__(16) bf16 Ph[2][64 * 40];   // phi tile [m][ci]
    __shared__ __align__(16) bf16 Gt[2][32 * 72];   // g tile   [ci][m]
    __shared__ float cvA[2048];                     // colinv for this m-half
    int tid = threadIdx.x;
    int lane = tid & 31, w = tid >> 5;
    int wq = w & 3, mh = w >> 2;
    int g = lane >> 2, tg = lane & 3;
    int b = blockIdx.y;
    int hb = blockIdx.z;
    int n0 = blockIdx.x * 64;
    const bf16* thB = g_theta + (size_t)b * N_ * CI;
    const bf16* phB = g_phi + (size_t)b * N_ * CI + (size_t)hb * 2048 * CI;
    const bf16* gB = g_gy + (size_t)b * CI * N_ + hb * 2048;
    const float* cp0 = g_colpart[0] + (size_t)b * N_ + hb * 2048;
    const float* cp1 = g_colpart[1] + (size_t)b * N_ + hb * 2048;

    for (int i = tid; i < 2048; i += 256) cvA[i] = 1.0f / (cp0[i] + cp1[i]);

    uint32_t a[2][4];
    {
        const bf16* Ar = thB + (size_t)(n0 + wq * 16) * CI;
#pragma unroll
        for (int kk = 0; kk < 2; kk++) {
            a[kk][0] = *(const uint32_t*)(Ar + (size_t)g * CI + kk * 16 + tg * 2);
            a[kk][1] = *(const uint32_t*)(Ar + (size_t)(g + 8) * CI + kk * 16 + tg * 2);
            a[kk][2] = *(const uint32_t*)(Ar + (size_t)g * CI + kk * 16 + tg * 2 + 8);
            a[kk][3] = *(const uint32_t*)(Ar + (size_t)(g + 8) * CI + kk * 16 + tg * 2 + 8);
        }
    }
    float x1[4][4];
#pragma unroll
    for (int i = 0; i < 4; i++)
#pragma unroll
        for (int k = 0; k < 4; k++) x1[i][k] = 0.f;

    auto issue = [&](int mt, int bufi) {
        const bf16* ps = phB + (size_t)mt * 64 * CI;
        const bf16* gs = gB + mt * 64;
        {   // phi: 64 rows x 32 ci
            int r = tid >> 2, q = tid & 3;
            cp16(&Ph[bufi][r * 40 + q * 8], ps + (size_t)r * CI + q * 8);
        }
        {   // g: 32 rows x 64 m
            int r = tid >> 3, q = tid & 7;
            cp16(&Gt[bufi][r * 72 + q * 8], gs + (size_t)r * N_ + q * 8);
        }
    };

    issue(0, 0);
    CP_COMMIT;
    for (int mt = 0; mt < 32; ++mt) {
        CP_WAIT0;
        __syncthreads();
        if (mt + 1 < 32) { issue(mt + 1, (mt + 1) & 1); CP_COMMIT; }
        int bufi = mt & 1;
        uint32_t ap[2][4];
#pragma unroll
        for (int j = 0; j < 4; j++) {
            int pr = mh * 32 + j * 8;
            uint32_t bp[2][2];
#pragma unroll
            for (int kk = 0; kk < 2; kk++) {
                const bf16* p = Ph[bufi] + (pr + g) * 40 + kk * 16 + tg * 2;
                bp[kk][0] = *(const uint32_t*)p;
                bp[kk][1] = *(const uint32_t*)(p + 8);
            }
            float c[4] = {0.f, 0.f, 0.f, 0.f};
            mma16816(c, a[0], bp[0]);
            mma16816(c, a[1], bp[1]);
            float2 cvp = *(const float2*)&cvA[mt * 64 + pr + tg * 2];
            float p0 = ex2f(c[0]) * cvp.x;
            float p1 = ex2f(c[1]) * cvp.y;
            float p2 = ex2f(c[2]) * cvp.x;
            float p3 = ex2f(c[3]) * cvp.y;
            int kt = j >> 1;
            int o = (j & 1) ? 2 : 0;
            ap[kt][o] = pack_bf2(p0, p1);
            ap[kt][o + 1] = pack_bf2(p2, p3);
        }
#pragma unroll
        for (int cc = 0; cc < 4; cc++)
#pragma unroll
            for (int kt = 0; kt < 2; kt++) {
                uint32_t bg[2];
                const bf16* p = Gt[bufi] + (cc * 8 + g) * 72 + mh * 32 + kt * 16 + tg * 2;
                bg[0] = *(const uint32_t*)p;
                bg[1] = *(const uint32_t*)(p + 8);
                mma16816(x1[cc], ap[kt], bg);
            }
    }

    // write bf16 partial x1 for quarter q = hb*2 + mh
    int q = hb * 2 + mh;
    bf16* dst = g_x1p + ((size_t)(b * 4 + q) * N_) * CI;
    int nlo = n0 + wq * 16 + g;
#pragma unroll
    for (int cc = 0; cc < 4; cc++) {
        int col = cc * 8 + tg * 2;
        *(uint32_t*)&dst[(size_t)nlo * CI + col] = pack_bf2(x1[cc][0], x1[cc][1]);
        *(uint32_t*)&dst[(size_t)(nlo + 8) * CI + col] = pack_bf2(x1[cc][2], x1[cc][3]);
    }
}

// ---------------------------------------------------------------------------
// fin: grid (N/32, B), block 128 (4 warps: 2 row-groups x 2 c-halves).
// Quarter slab for this n-tile = 32 rows x 32 ci bf16 = 2048 B = 128 uint4.
// One uint4 per thread per quarter -> 4 independent LDG.128/thread.
// z = supp + x1 * W^T + wb via mma epilogue.
// ---------------------------------------------------------------------------
__global__ __launch_bounds__(128) void fin_kernel(
    const float* __restrict__ supp, const float* __restrict__ ww,
    const float* __restrict__ wb, float* __restrict__ zout) {
    __shared__ __align__(16) bf16 X[32 * 40];
    __shared__ __align__(16) bf16 Ws[64 * 40];
    __shared__ float wbs[64];
    int tid = threadIdx.x;
    int lane = tid & 31, w = tid >> 5;
    int wq = w & 1, ch = w >> 1;
    int g = lane >> 2, tg = lane & 3;
    int b = blockIdx.y;
    int n0 = blockIdx.x * 32;

    for (int i = tid; i < C_ * CI; i += 128)
        Ws[(i >> 5) * 40 + (i & 31)] = __float2bfloat16(ww[i]);
    if (tid < 64) wbs[tid] = wb[tid];

    {
        uint4 v[4];
#pragma unroll
        for (int qq = 0; qq < 4; qq++) {
            const uint4* src = (const uint4*)(g_x1p + ((size_t)(b * 4 + qq) * N_ + n0) * CI);
            v[qq] = src[tid];
        }
        int r = tid >> 2, q = tid & 3;  // row 0..31, uint4-within-row 0..3
        uint32_t out[4];
#pragma unroll
        for (int e = 0; e < 4; e++) {
            float2 s = make_float2(0.f, 0.f);
#pragma unroll
            for (int qq = 0; qq < 4; qq++) {
                uint32_t u = ((const uint32_t*)&v[qq])[e];
                float2 t = __bfloat1622float2(*(const __nv_bfloat162*)&u);
                s.x += t.x; s.y += t.y;
            }
            out[e] = pack_bf2(s.x, s.y);
        }
        uint32_t* dst = (uint32_t*)&X[r * 40] + q * 4;  // q*4 in {0,4,8,12} < 16
        dst[0] = out[0]; dst[1] = out[1]; dst[2] = out[2]; dst[3] = out[3];
    }
    __syncthreads();

    uint32_t ax[2][4];
    const bf16* Ar = X + (wq * 16) * 40;
#pragma unroll
    for (int kk = 0; kk < 2; kk++) {
        ax[kk][0] = *(const uint32_t*)(Ar + g * 40 + kk * 16 + tg * 2);
        ax[kk][1] = *(const uint32_t*)(Ar + (g + 8) * 40 + kk * 16 + tg * 2);
        ax[kk][2] = *(const uint32_t*)(Ar + g * 40 + kk * 16 + tg * 2 + 8);
        ax[kk][3] = *(const uint32_t*)(Ar + (g + 8) * 40 + kk * 16 + tg * 2 + 8);
    }
#pragma unroll
    for (int i = 0; i < 4; i++) {
        int cc2 = ch * 4 + i;
        float zc[4] = {0.f, 0.f, 0.f, 0.f};
#pragma unroll
        for (int kk = 0; kk < 2; kk++) {
            uint32_t bw[2];
            const bf16* p = Ws + (cc2 * 8 + g) * 40 + kk * 16 + tg * 2;
            bw[0] = *(const uint32_t*)p;
            bw[1] = *(const uint32_t*)(p + 8);
            mma16816(zc, ax[kk], bw);
        }
        int c = cc2 * 8 + tg * 2;
        int n = n0 + wq * 16 + g;
        size_t base = ((size_t)b * C_ + c) * N_ + n;
        zout[base] = zc[0] + wbs[c] + supp[base];
        zout[base + N_] = zc[1] + wbs[c + 1] + supp[base + N_];
        zout[base + 8] = zc[2] + wbs[c] + supp[base + 8];
        zout[base + N_ + 8] = zc[3] + wbs[c + 1] + supp[base + N_ + 8];
    }
}

extern "C" void kernel_launch(void* const* d_in, const int* in_sizes, int n_in,
                              void* d_out, int out_size) {
    const float* supp = (const float*)d_in[0];
    const float* ref = (const float*)d_in[1];
    const float* tw = (const float*)d_in[2];
    const float* tb = (const float*)d_in[3];
    const float* pw = (const float*)d_in[4];
    const float* pb = (const float*)d_in[5];
    const float* gw = (const float*)d_in[6];
    const float* gb = (const float*)d_in[7];
    const float* ww = (const float*)d_in[8];
    const float* wb = (const float*)d_in[9];
    float* z = (float*)d_out;

    prep_kernel<<<dim3(N_ / 256, B_, 6), 256>>>(supp, ref, tw, tb, pw, pb, gw, gb);
    pass1_kernel<<<dim3(N_ / 64, B_, 2), 256>>>();
    pass2_kernel<<<dim3(N_ / 64, B_, 2), 256>>>();
    fin_kernel<<<dim3(N_ / 32, B_), 128>>>(supp, ww, wb, z);
}

// round 10
// speedup vs baseline: 1.0121x; 1.0121x over previous
#include <cuda_runtime.h>
#include <cuda_bf16.h>
#include <cstdint>

// NonLocalBlock: B=4, C=64, Ci=32, H=W=64, N=4096
// z = supp + W( softmax_n(theta(supp)^T phi(ref)) @ g(ref) ) + wb
//
//  prep : projections (fp32 math, bf16 out); theta pre-scaled by log2(e); MLP16
//  pass1: partial colsum[m] = sum_n 2^f' per n-half (512 blocks)
//  init : zout = supp + wb (coalesced stream)
//  pass2: recompute S on an m-half, P = 2^f'*colinv, x1 partial, in-block
//         m-slice reduce, W-conv epilogue, RED.F32 accumulate into zout.
//         (W is linear: z = (supp+wb) + sum_halves x1_half * W^T)
// GEMMs via mma.sync.m16n8k16 bf16/fp32. No max-subtraction needed (f ~ N(0,1),
// |f| <~ 6 over 67M samples; softmax shift-invariant).

#define B_ 4
#define C_ 64
#define CI 32
#define N_ 4096
#define LOG2E 1.4426950408889634f

typedef __nv_bfloat16 bf16;

__device__ __align__(16) bf16 g_theta[B_ * N_ * CI];    // [b][n][ci] (x log2e)
__device__ __align__(16) bf16 g_phi[B_ * N_ * CI];      // [b][m][ci]
__device__ __align__(16) bf16 g_gy[B_ * CI * N_];       // [b][ci][m]
__device__ __align__(16) float g_colpart[2][B_ * N_];   // [half][b][m]

__device__ __forceinline__ uint32_t pack_bf2(float x, float y) {
    __nv_bfloat162 h = __float22bfloat162_rn(make_float2(x, y));
    return *reinterpret_cast<uint32_t*>(&h);
}

__device__ __forceinline__ float ex2f(float x) {
    float y;
    asm("ex2.approx.ftz.f32 %0, %1;" : "=f"(y) : "f"(x));
    return y;
}

__device__ __forceinline__ void mma16816(float* c, const uint32_t* a, const uint32_t* b) {
    asm volatile(
        "mma.sync.aligned.m16n8k16.row.col.f32.bf16.bf16.f32 "
        "{%0,%1,%2,%3}, {%4,%5,%6,%7}, {%8,%9}, {%0,%1,%2,%3};\n"
        : "+f"(c[0]), "+f"(c[1]), "+f"(c[2]), "+f"(c[3])
        : "r"(a[0]), "r"(a[1]), "r"(a[2]), "r"(a[3]), "r"(b[0]), "r"(b[1]));
}

__device__ __forceinline__ void cp16(void* dst, const void* src) {
    uint32_t s = (uint32_t)__cvta_generic_to_shared(dst);
    asm volatile("cp.async.cg.shared.global [%0], [%1], 16;\n" :: "r"(s), "l"(src));
}
#define CP_COMMIT asm volatile("cp.async.commit_group;\n")
#define CP_WAIT0  asm volatile("cp.async.wait_group 0;\n")

// ---------------------------------------------------------------------------
// prep: grid (N/256, B, 6), block 256. z = proj*2 + half; 16 outputs/thread.
// ---------------------------------------------------------------------------
__global__ __launch_bounds__(256) void prep_kernel(
    const float* __restrict__ supp, const float* __restrict__ ref,
    const float* __restrict__ tw, const float* __restrict__ tb,
    const float* __restrict__ pw, const float* __restrict__ pb,
    const float* __restrict__ gw, const float* __restrict__ gb) {
    __shared__ float sw[16 * C_];
    __shared__ float sb[16];
    int tid = threadIdx.x;
    int z = blockIdx.z;
    int proj = z >> 1, half = z & 1;
    const float* wsel = (proj == 0) ? tw : (proj == 1) ? pw : gw;
    const float* bsel = (proj == 0) ? tb : (proj == 1) ? pb : gb;
    const float* xsel = (proj == 0) ? supp : ref;
    for (int i = tid; i < 16 * C_; i += 256) sw[i] = wsel[half * 16 * C_ + i];
    if (tid < 16) sb[tid] = bsel[half * 16 + tid];
    __syncthreads();

    int b = blockIdx.y;
    int n = blockIdx.x * 256 + tid;
    const float* xp = xsel + (size_t)b * C_ * N_ + n;

    float acc[16];
#pragma unroll
    for (int i = 0; i < 16; i++) acc[i] = sb[i];
#pragma unroll
    for (int c0 = 0; c0 < C_; c0 += 16) {
        float v[16];
#pragma unroll
        for (int k = 0; k < 16; k++) v[k] = xp[(size_t)(c0 + k) * N_];
#pragma unroll
        for (int k = 0; k < 16; k++)
#pragma unroll
            for (int i = 0; i < 16; i++) acc[i] += sw[i * C_ + c0 + k] * v[k];
    }

    if (proj == 0) {
#pragma unroll
        for (int i = 0; i < 16; i++) acc[i] *= LOG2E;
        uint32_t* dst = (uint32_t*)(g_theta + (size_t)b * N_ * CI) + (size_t)n * 16 + half * 8;
#pragma unroll
        for (int i = 0; i < 8; i++) dst[i] = pack_bf2(acc[2 * i], acc[2 * i + 1]);
    } else if (proj == 1) {
        uint32_t* dst = (uint32_t*)(g_phi + (size_t)b * N_ * CI) + (size_t)n * 16 + half * 8;
#pragma unroll
        for (int i = 0; i < 8; i++) dst[i] = pack_bf2(acc[2 * i], acc[2 * i + 1]);
    } else {
#pragma unroll
        for (int i = 0; i < 16; i++)
            g_gy[(size_t)b * CI * N_ + (size_t)(half * 16 + i) * N_ + n] = __float2bfloat16(acc[i]);
    }
}

// ---------------------------------------------------------------------------
// init: zout = supp + wb. 1M floats, float4 stream. grid 512, block 256.
// ---------------------------------------------------------------------------
__global__ __launch_bounds__(256) void init_kernel(
    const float* __restrict__ supp, const float* __restrict__ wb,
    float* __restrict__ zout) {
    int idx = blockIdx.x * 512 + threadIdx.x;  // float4 index, 2 per thread
    const float4* s4 = (const float4*)supp;
    float4* z4 = (float4*)zout;
#pragma unroll
    for (int k = 0; k < 2; k++) {
        int i = idx + k * 256;
        int c = (i >> 10) & (C_ - 1);  // i / (N_/4) % C_
        float b = __ldg(&wb[c]);
        float4 v = s4[i];
        v.x += b; v.y += b; v.z += b; v.w += b;
        z4[i] = v;
    }
}

// ---------------------------------------------------------------------------
// pass1: grid (N/64 m-tiles, B, 2 n-halves), block 256 (8 warps x 16 rows).
// ---------------------------------------------------------------------------
__global__ __launch_bounds__(256) void pass1_kernel() {
    __shared__ __align__(16) bf16 At[2][128 * 40];
    __shared__ float cs[64];
    int tid = threadIdx.x;
    int lane = tid & 31, w = tid >> 5;
    int g = lane >> 2, tg = lane & 3;
    int b = blockIdx.y;
    int half = blockIdx.z;
    int m0 = blockIdx.x * 64;
    const bf16* thB = g_theta + (size_t)b * N_ * CI + (size_t)half * 2048 * CI;
    const bf16* phB = g_phi + (size_t)b * N_ * CI;

    uint32_t bfr[8][2][2];
#pragma unroll
    for (int j = 0; j < 8; j++)
#pragma unroll
        for (int kk = 0; kk < 2; kk++) {
            const bf16* p = phB + (size_t)(m0 + j * 8 + g) * CI + kk * 16 + tg * 2;
            bfr[j][kk][0] = *(const uint32_t*)p;
            bfr[j][kk][1] = *(const uint32_t*)(p + 8);
        }
    float part[16];
#pragma unroll
    for (int i = 0; i < 16; i++) part[i] = 0.f;
    if (tid < 64) cs[tid] = 0.f;

    {   // prologue: theta tile 0
        int i0 = tid, i1 = tid + 256;
        cp16(&At[0][(i0 >> 2) * 40 + (i0 & 3) * 8], thB + (size_t)(i0 >> 2) * CI + (i0 & 3) * 8);
        cp16(&At[0][(i1 >> 2) * 40 + (i1 & 3) * 8], thB + (size_t)(i1 >> 2) * CI + (i1 & 3) * 8);
        CP_COMMIT;
    }
    for (int nt = 0; nt < 16; ++nt) {
        CP_WAIT0;
        __syncthreads();
        if (nt + 1 < 16) {
            const bf16* s = thB + (size_t)(nt + 1) * 128 * CI;
            bf16* d = At[(nt + 1) & 1];
            int i0 = tid, i1 = tid + 256;
            cp16(&d[(i0 >> 2) * 40 + (i0 & 3) * 8], s + (size_t)(i0 >> 2) * CI + (i0 & 3) * 8);
            cp16(&d[(i1 >> 2) * 40 + (i1 & 3) * 8], s + (size_t)(i1 >> 2) * CI + (i1 & 3) * 8);
            CP_COMMIT;
        }
        uint32_t a[2][4];
        const bf16* Ar = At[nt & 1] + (w * 16) * 40;
#pragma unroll
        for (int kk = 0; kk < 2; kk++) {
            a[kk][0] = *(const uint32_t*)(Ar + g * 40 + kk * 16 + tg * 2);
            a[kk][1] = *(const uint32_t*)(Ar + (g + 8) * 40 + kk * 16 + tg * 2);
            a[kk][2] = *(const uint32_t*)(Ar + g * 40 + kk * 16 + tg * 2 + 8);
            a[kk][3] = *(const uint32_t*)(Ar + (g + 8) * 40 + kk * 16 + tg * 2 + 8);
        }
#pragma unroll
        for (int j = 0; j < 8; j++) {
            float c[4] = {0.f, 0.f, 0.f, 0.f};
            mma16816(c, a[0], bfr[j][0]);
            mma16816(c, a[1], bfr[j][1]);
            part[j * 2] += ex2f(c[0]) + ex2f(c[2]);
            part[j * 2 + 1] += ex2f(c[1]) + ex2f(c[3]);
        }
    }
#pragma unroll
    for (int off = 4; off <= 16; off <<= 1)
#pragma unroll
        for (int i = 0; i < 16; i++) part[i] += __shfl_xor_sync(0xffffffffu, part[i], off);
    __syncthreads();
    if (g == 0) {
#pragma unroll
        for (int j = 0; j < 8; j++) {
            atomicAdd(&cs[j * 8 + tg * 2], part[j * 2]);
            atomicAdd(&cs[j * 8 + tg * 2 + 1], part[j * 2 + 1]);
        }
    }
    __syncthreads();
    if (tid < 64) g_colpart[half][(size_t)b * N_ + m0 + tid] = cs[tid];
}

// ---------------------------------------------------------------------------
// pass2: grid (N/64 n-tiles, B, 2 m-halves), block 256 (8 warps).
// Warp w: row-group wq=w&3 (rows n0+wq*16), mh=w>>2 (32-wide slice of 64-tile).
// Recomputes S on its 2048-wide m-half; P=2^f'*colinv; x1 partial; in-block
// mh reduce; W-conv epilogue; RED.F32 into zout (pre-initialized supp+wb).
// ---------------------------------------------------------------------------
__global__ __launch_bounds__(256) void pass2_kernel(
    const float* __restrict__ ww, float* __restrict__ zout) {
    __shared__ __align__(16) bf16 Ph[2][64 * 40];   // phi tile [m][ci]
    __shared__ __align__(16) bf16 Gt[2][32 * 72];   // g tile   [ci][m]
    __shared__ float cvA[2048];                     // colinv for this m-half
    __shared__ __align__(16) bf16 Ws[64 * 40];      // w weights [c][ci]
    float* xr = (float*)Ph;                         // alias after mainloop
    int tid = threadIdx.x;
    int lane = tid & 31, w = tid >> 5;
    int wq = w & 3, mh = w >> 2;
    int g = lane >> 2, tg = lane & 3;
    int b = blockIdx.y;
    int hb = blockIdx.z;
    int n0 = blockIdx.x * 64;
    const bf16* thB = g_theta + (size_t)b * N_ * CI;
    const bf16* phB = g_phi + (size_t)b * N_ * CI + (size_t)hb * 2048 * CI;
    const bf16* gB = g_gy + (size_t)b * CI * N_ + hb * 2048;
    const float* cp0 = g_colpart[0] + (size_t)b * N_ + hb * 2048;
    const float* cp1 = g_colpart[1] + (size_t)b * N_ + hb * 2048;

    for (int i = tid; i < 2048; i += 256) cvA[i] = 1.0f / (cp0[i] + cp1[i]);
    for (int i = tid; i < C_ * CI; i += 256)
        Ws[(i >> 5) * 40 + (i & 31)] = __float2bfloat16(ww[i]);

    uint32_t a[2][4];
    {
        const bf16* Ar = thB + (size_t)(n0 + wq * 16) * CI;
#pragma unroll
        for (int kk = 0; kk < 2; kk++) {
            a[kk][0] = *(const uint32_t*)(Ar + (size_t)g * CI + kk * 16 + tg * 2);
            a[kk][1] = *(const uint32_t*)(Ar + (size_t)(g + 8) * CI + kk * 16 + tg * 2);
            a[kk][2] = *(const uint32_t*)(Ar + (size_t)g * CI + kk * 16 + tg * 2 + 8);
            a[kk][3] = *(const uint32_t*)(Ar + (size_t)(g + 8) * CI + kk * 16 + tg * 2 + 8);
        }
    }
    float x1[4][4];
#pragma unroll
    for (int i = 0; i < 4; i++)
#pragma unroll
        for (int k = 0; k < 4; k++) x1[i][k] = 0.f;

    auto issue = [&](int mt, int bufi) {
        const bf16* ps = phB + (size_t)mt * 64 * CI;
        const bf16* gs = gB + mt * 64;
        {   // phi: 64 rows x 32 ci
            int r = tid >> 2, q = tid & 3;
            cp16(&Ph[bufi][r * 40 + q * 8], ps + (size_t)r * CI + q * 8);
        }
        {   // g: 32 rows x 64 m
            int r = tid >> 3, q = tid & 7;
            cp16(&Gt[bufi][r * 72 + q * 8], gs + (size_t)r * N_ + q * 8);
        }
    };

    issue(0, 0);
    CP_COMMIT;
    for (int mt = 0; mt < 32; ++mt) {
        CP_WAIT0;
        __syncthreads();
        if (mt + 1 < 32) { issue(mt + 1, (mt + 1) & 1); CP_COMMIT; }
        int bufi = mt & 1;
        uint32_t ap[2][4];
#pragma unroll
        for (int j = 0; j < 4; j++) {
            int pr = mh * 32 + j * 8;
            uint32_t bp[2][2];
#pragma unroll
            for (int kk = 0; kk < 2; kk++) {
                const bf16* p = Ph[bufi] + (pr + g) * 40 + kk * 16 + tg * 2;
                bp[kk][0] = *(const uint32_t*)p;
                bp[kk][1] = *(const uint32_t*)(p + 8);
            }
            float c[4] = {0.f, 0.f, 0.f, 0.f};
            mma16816(c, a[0], bp[0]);
            mma16816(c, a[1], bp[1]);
            float2 cvp = *(const float2*)&cvA[mt * 64 + pr + tg * 2];
            float p0 = ex2f(c[0]) * cvp.x;
            float p1 = ex2f(c[1]) * cvp.y;
            float p2 = ex2f(c[2]) * cvp.x;
            float p3 = ex2f(c[3]) * cvp.y;
            int kt = j >> 1;
            int o = (j & 1) ? 2 : 0;
            ap[kt][o] = pack_bf2(p0, p1);
            ap[kt][o + 1] = pack_bf2(p2, p3);
        }
#pragma unroll
        for (int cc = 0; cc < 4; cc++)
#pragma unroll
            for (int kt = 0; kt < 2; kt++) {
                uint32_t bg[2];
                const bf16* p = Gt[bufi] + (cc * 8 + g) * 72 + mh * 32 + kt * 16 + tg * 2;
                bg[0] = *(const uint32_t*)p;
                bg[1] = *(const uint32_t*)(p + 8);
                mma16816(x1[cc], ap[kt], bg);
            }
    }

    // in-block mh reduce (xr aliases dead Ph tiles)
    __syncthreads();
    if (mh == 1) {
        float* dst = xr + (wq * 32 + lane) * 17;
#pragma unroll
        for (int cc = 0; cc < 4; cc++)
#pragma unroll
            for (int k = 0; k < 4; k++) dst[cc * 4 + k] = x1[cc][k];
    }
    __syncthreads();
    if (mh == 0) {
        const float* src = xr + (wq * 32 + lane) * 17;
#pragma unroll
        for (int cc = 0; cc < 4; cc++)
#pragma unroll
            for (int k = 0; k < 4; k++) x1[cc][k] += src[cc * 4 + k];

        // W-conv epilogue on this half's x1, RED into zout
        uint32_t ax[2][4];
#pragma unroll
        for (int cc = 0; cc < 4; cc++) {
            int kt = cc >> 1;
            int o = (cc & 1) ? 2 : 0;
            ax[kt][o] = pack_bf2(x1[cc][0], x1[cc][1]);
            ax[kt][o + 1] = pack_bf2(x1[cc][2], x1[cc][3]);
        }
#pragma unroll
        for (int cc2 = 0; cc2 < 8; cc2++) {
            float zc[4] = {0.f, 0.f, 0.f, 0.f};
#pragma unroll
            for (int kk = 0; kk < 2; kk++) {
                uint32_t bw[2];
                const bf16* p = Ws + (cc2 * 8 + g) * 40 + kk * 16 + tg * 2;
                bw[0] = *(const uint32_t*)p;
                bw[1] = *(const uint32_t*)(p + 8);
                mma16816(zc, ax[kk], bw);
            }
            int c = cc2 * 8 + tg * 2;
            int n = n0 + wq * 16 + g;
            size_t base = ((size_t)b * C_ + c) * N_ + n;
            atomicAdd(&zout[base], zc[0]);
            atomicAdd(&zout[base + N_], zc[1]);
            atomicAdd(&zout[base + 8], zc[2]);
            atomicAdd(&zout[base + N_ + 8], zc[3]);
        }
    }
}

extern "C" void kernel_launch(void* const* d_in, const int* in_sizes, int n_in,
                              void* d_out, int out_size) {
    const float* supp = (const float*)d_in[0];
    const float* ref = (const float*)d_in[1];
    const float* tw = (const float*)d_in[2];
    const float* tb = (const float*)d_in[3];
    const float* pw = (const float*)d_in[4];
    const float* pb = (const float*)d_in[5];
    const float* gw = (const float*)d_in[6];
    const float* gb = (const float*)d_in[7];
    const float* ww = (const float*)d_in[8];
    const float* wb = (const float*)d_in[9];
    float* z = (float*)d_out;

    prep_kernel<<<dim3(N_ / 256, B_, 6), 256>>>(supp, ref, tw, tb, pw, pb, gw, gb);
    init_kernel<<<512, 256>>>(supp, wb, z);
    pass1_kernel<<<dim3(N_ / 64, B_, 2), 256>>>();
    pass2_kernel<<<dim3(N_ / 64, B_, 2), 256>>>(ww, z);
}

// round 11
// speedup vs baseline: 1.0967x; 1.0836x over previous
#include <cuda_runtime.h>
#include <cuda_bf16.h>
#include <cstdint>

// NonLocalBlock: B=4, C=64, Ci=32, H=W=64, N=4096
// z = supp + W( softmax_n(theta(supp)^T phi(ref)) @ g(ref) ) + wb
//
//  prep : projections (fp32 math, bf16 out); theta pre-scaled by log2(e); MLP16
//  pass1: partial colsum[m] = sum_n 2^f' per n-half (512 blocks), ldmatrix A-frags
//  init : zout = supp + wb (coalesced stream)
//  pass2: recompute S on an m-half, P = 2^f'*colinv, x1 partial, in-block
//         m-slice reduce, W-conv epilogue, RED.F32 into zout. ldmatrix frags.
// GEMMs via mma.sync.m16n8k16 bf16/fp32. No max-subtraction needed (f ~ N(0,1),
// |f| <~ 6 over 67M samples; softmax shift-invariant).

#define B_ 4
#define C_ 64
#define CI 32
#define N_ 4096
#define LOG2E 1.4426950408889634f

typedef __nv_bfloat16 bf16;

__device__ __align__(16) bf16 g_theta[B_ * N_ * CI];    // [b][n][ci] (x log2e)
__device__ __align__(16) bf16 g_phi[B_ * N_ * CI];      // [b][m][ci]
__device__ __align__(16) bf16 g_gy[B_ * CI * N_];       // [b][ci][m]
__device__ __align__(16) float g_colpart[2][B_ * N_];   // [half][b][m]

__device__ __forceinline__ uint32_t pack_bf2(float x, float y) {
    __nv_bfloat162 h = __float22bfloat162_rn(make_float2(x, y));
    return *reinterpret_cast<uint32_t*>(&h);
}

__device__ __forceinline__ float ex2f(float x) {
    float y;
    asm("ex2.approx.ftz.f32 %0, %1;" : "=f"(y) : "f"(x));
    return y;
}

__device__ __forceinline__ uint32_t smem_u32(const void* p) {
    return (uint32_t)__cvta_generic_to_shared(p);
}

__device__ __forceinline__ void ldsm_x4(uint32_t* r, uint32_t addr) {
    asm volatile("ldmatrix.sync.aligned.m8n8.x4.shared.b16 {%0,%1,%2,%3}, [%4];"
        : "=r"(r[0]), "=r"(r[1]), "=r"(r[2]), "=r"(r[3]) : "r"(addr));
}

__device__ __forceinline__ void mma16816(float* c, const uint32_t* a, const uint32_t* b) {
    asm volatile(
        "mma.sync.aligned.m16n8k16.row.col.f32.bf16.bf16.f32 "
        "{%0,%1,%2,%3}, {%4,%5,%6,%7}, {%8,%9}, {%0,%1,%2,%3};\n"
        : "+f"(c[0]), "+f"(c[1]), "+f"(c[2]), "+f"(c[3])
        : "r"(a[0]), "r"(a[1]), "r"(a[2]), "r"(a[3]), "r"(b[0]), "r"(b[1]));
}

__device__ __forceinline__ void cp16(void* dst, const void* src) {
    uint32_t s = (uint32_t)__cvta_generic_to_shared(dst);
    asm volatile("cp.async.cg.shared.global [%0], [%1], 16;\n" :: "r"(s), "l"(src));
}
#define CP_COMMIT asm volatile("cp.async.commit_group;\n")
#define CP_WAIT0  asm volatile("cp.async.wait_group 0;\n")

// ---------------------------------------------------------------------------
// prep: grid (N/256, B, 6), block 256. z = proj*2 + half; 16 outputs/thread.
// ---------------------------------------------------------------------------
__global__ __launch_bounds__(256) void prep_kernel(
    const float* __restrict__ supp, const float* __restrict__ ref,
    const float* __restrict__ tw, const float* __restrict__ tb,
    const float* __restrict__ pw, const float* __restrict__ pb,
    const float* __restrict__ gw, const float* __restrict__ gb) {
    __shared__ float sw[16 * C_];
    __shared__ float sb[16];
    int tid = threadIdx.x;
    int z = blockIdx.z;
    int proj = z >> 1, half = z & 1;
    const float* wsel = (proj == 0) ? tw : (proj == 1) ? pw : gw;
    const float* bsel = (proj == 0) ? tb : (proj == 1) ? pb : gb;
    const float* xsel = (proj == 0) ? supp : ref;
    for (int i = tid; i < 16 * C_; i += 256) sw[i] = wsel[half * 16 * C_ + i];
    if (tid < 16) sb[tid] = bsel[half * 16 + tid];
    __syncthreads();

    int b = blockIdx.y;
    int n = blockIdx.x * 256 + tid;
    const float* xp = xsel + (size_t)b * C_ * N_ + n;

    float acc[16];
#pragma unroll
    for (int i = 0; i < 16; i++) acc[i] = sb[i];
#pragma unroll
    for (int c0 = 0; c0 < C_; c0 += 16) {
        float v[16];
#pragma unroll
        for (int k = 0; k < 16; k++) v[k] = xp[(size_t)(c0 + k) * N_];
#pragma unroll
        for (int k = 0; k < 16; k++)
#pragma unroll
            for (int i = 0; i < 16; i++) acc[i] += sw[i * C_ + c0 + k] * v[k];
    }

    if (proj == 0) {
#pragma unroll
        for (int i = 0; i < 16; i++) acc[i] *= LOG2E;
        uint32_t* dst = (uint32_t*)(g_theta + (size_t)b * N_ * CI) + (size_t)n * 16 + half * 8;
#pragma unroll
        for (int i = 0; i < 8; i++) dst[i] = pack_bf2(acc[2 * i], acc[2 * i + 1]);
    } else if (proj == 1) {
        uint32_t* dst = (uint32_t*)(g_phi + (size_t)b * N_ * CI) + (size_t)n * 16 + half * 8;
#pragma unroll
        for (int i = 0; i < 8; i++) dst[i] = pack_bf2(acc[2 * i], acc[2 * i + 1]);
    } else {
#pragma unroll
        for (int i = 0; i < 16; i++)
            g_gy[(size_t)b * CI * N_ + (size_t)(half * 16 + i) * N_ + n] = __float2bfloat16(acc[i]);
    }
}

// ---------------------------------------------------------------------------
// init: zout = supp + wb. 1M floats, float4 stream. grid 512, block 256.
// ---------------------------------------------------------------------------
__global__ __launch_bounds__(256) void init_kernel(
    const float* __restrict__ supp, const float* __restrict__ wb,
    float* __restrict__ zout) {
    int idx = blockIdx.x * 512 + threadIdx.x;
    const float4* s4 = (const float4*)supp;
    float4* z4 = (float4*)zout;
#pragma unroll
    for (int k = 0; k < 2; k++) {
        int i = idx + k * 256;
        int c = (i >> 10) & (C_ - 1);
        float b = __ldg(&wb[c]);
        float4 v = s4[i];
        v.x += b; v.y += b; v.z += b; v.w += b;
        z4[i] = v;
    }
}

// ---------------------------------------------------------------------------
// pass1: grid (N/64 m-tiles, B, 2 n-halves), block 256 (8 warps x 16 rows).
// A-fragments via 2x ldmatrix.x4 per iteration (was 16 scalar LDS).
// ---------------------------------------------------------------------------
__global__ __launch_bounds__(256) void pass1_kernel() {
    __shared__ __align__(16) bf16 At[2][128 * 40];
    __shared__ float cs[64];
    int tid = threadIdx.x;
    int lane = tid & 31, w = tid >> 5;
    int g = lane >> 2, tg = lane & 3;
    int b = blockIdx.y;
    int half = blockIdx.z;
    int m0 = blockIdx.x * 64;
    const bf16* thB = g_theta + (size_t)b * N_ * CI + (size_t)half * 2048 * CI;
    const bf16* phB = g_phi + (size_t)b * N_ * CI;

    uint32_t bfr[8][2][2];
#pragma unroll
    for (int j = 0; j < 8; j++)
#pragma unroll
        for (int kk = 0; kk < 2; kk++) {
            const bf16* p = phB + (size_t)(m0 + j * 8 + g) * CI + kk * 16 + tg * 2;
            bfr[j][kk][0] = *(const uint32_t*)p;
            bfr[j][kk][1] = *(const uint32_t*)(p + 8);
        }
    float part[16];
#pragma unroll
    for (int i = 0; i < 16; i++) part[i] = 0.f;
    if (tid < 64) cs[tid] = 0.f;

    // ldmatrix lane address offset (bytes) into the theta tile:
    // matrix q: rows w*16 + (q&1)*8 + r8, k elem (q>>1)*8  (+ kk*16 elems)
    int r8 = lane & 7, q8 = lane >> 3;
    uint32_t aoff = ((w * 16 + (q8 & 1) * 8 + r8) * 40 + (q8 >> 1) * 8) * 2;

    {   // prologue: theta tile 0
        int i0 = tid, i1 = tid + 256;
        cp16(&At[0][(i0 >> 2) * 40 + (i0 & 3) * 8], thB + (size_t)(i0 >> 2) * CI + (i0 & 3) * 8);
        cp16(&At[0][(i1 >> 2) * 40 + (i1 & 3) * 8], thB + (size_t)(i1 >> 2) * CI + (i1 & 3) * 8);
        CP_COMMIT;
    }
    for (int nt = 0; nt < 16; ++nt) {
        CP_WAIT0;
        __syncthreads();
        if (nt + 1 < 16) {
            const bf16* s = thB + (size_t)(nt + 1) * 128 * CI;
            bf16* d = At[(nt + 1) & 1];
            int i0 = tid, i1 = tid + 256;
            cp16(&d[(i0 >> 2) * 40 + (i0 & 3) * 8], s + (size_t)(i0 >> 2) * CI + (i0 & 3) * 8);
            cp16(&d[(i1 >> 2) * 40 + (i1 & 3) * 8], s + (size_t)(i1 >> 2) * CI + (i1 & 3) * 8);
            CP_COMMIT;
        }
        uint32_t a[2][4];
        uint32_t abase = smem_u32(At[nt & 1]) + aoff;
        ldsm_x4(a[0], abase);
        ldsm_x4(a[1], abase + 32);  // kk=1: +16 elems = +32 bytes
#pragma unroll
        for (int j = 0; j < 8; j++) {
            float c[4] = {0.f, 0.f, 0.f, 0.f};
            mma16816(c, a[0], bfr[j][0]);
            mma16816(c, a[1], bfr[j][1]);
            part[j * 2] += ex2f(c[0]) + ex2f(c[2]);
            part[j * 2 + 1] += ex2f(c[1]) + ex2f(c[3]);
        }
    }
#pragma unroll
    for (int off = 4; off <= 16; off <<= 1)
#pragma unroll
        for (int i = 0; i < 16; i++) part[i] += __shfl_xor_sync(0xffffffffu, part[i], off);
    __syncthreads();
    if (g == 0) {
#pragma unroll
        for (int j = 0; j < 8; j++) {
            atomicAdd(&cs[j * 8 + tg * 2], part[j * 2]);
            atomicAdd(&cs[j * 8 + tg * 2 + 1], part[j * 2 + 1]);
        }
    }
    __syncthreads();
    if (tid < 64) g_colpart[half][(size_t)b * N_ + m0 + tid] = cs[tid];
}

// ---------------------------------------------------------------------------
// pass2: grid (N/64 n-tiles, B, 2 m-halves), block 256 (8 warps).
// Warp w: row-group wq=w&3, m-slice mh=w>>2 (32-wide). phi/g fragments via
// ldmatrix.x4 (was 32 scalar LDS per iter). RED.F32 epilogue into zout.
// ---------------------------------------------------------------------------
__global__ __launch_bounds__(256) void pass2_kernel(
    const float* __restrict__ ww, float* __restrict__ zout) {
    __shared__ __align__(16) bf16 Ph[2][64 * 40];   // phi tile [m][ci]
    __shared__ __align__(16) bf16 Gt[2][32 * 72];   // g tile   [ci][m]
    __shared__ float cvA[2048];                     // colinv for this m-half
    __shared__ __align__(16) bf16 Ws[64 * 40];      // w weights [c][ci]
    float* xr = (float*)Ph;                         // alias after mainloop
    int tid = threadIdx.x;
    int lane = tid & 31, w = tid >> 5;
    int wq = w & 3, mh = w >> 2;
    int g = lane >> 2, tg = lane & 3;
    int b = blockIdx.y;
    int hb = blockIdx.z;
    int n0 = blockIdx.x * 64;
    const bf16* thB = g_theta + (size_t)b * N_ * CI;
    const bf16* phB = g_phi + (size_t)b * N_ * CI + (size_t)hb * 2048 * CI;
    const bf16* gB = g_gy + (size_t)b * CI * N_ + hb * 2048;
    const float* cp0 = g_colpart[0] + (size_t)b * N_ + hb * 2048;
    const float* cp1 = g_colpart[1] + (size_t)b * N_ + hb * 2048;

    for (int i = tid; i < 2048; i += 256) cvA[i] = 1.0f / (cp0[i] + cp1[i]);
    for (int i = tid; i < C_ * CI; i += 256)
        Ws[(i >> 5) * 40 + (i & 31)] = __float2bfloat16(ww[i]);

    uint32_t a[2][4];
    {
        const bf16* Ar = thB + (size_t)(n0 + wq * 16) * CI;
#pragma unroll
        for (int kk = 0; kk < 2; kk++) {
            a[kk][0] = *(const uint32_t*)(Ar + (size_t)g * CI + kk * 16 + tg * 2);
            a[kk][1] = *(const uint32_t*)(Ar + (size_t)(g + 8) * CI + kk * 16 + tg * 2);
            a[kk][2] = *(const uint32_t*)(Ar + (size_t)g * CI + kk * 16 + tg * 2 + 8);
            a[kk][3] = *(const uint32_t*)(Ar + (size_t)(g + 8) * CI + kk * 16 + tg * 2 + 8);
        }
    }
    float x1[4][4];
#pragma unroll
    for (int i = 0; i < 4; i++)
#pragma unroll
        for (int k = 0; k < 4; k++) x1[i][k] = 0.f;

    // ldmatrix lane offsets (bytes):
    // bp (per j): row mh*32 + j*8 + r8 in Ph (stride 40), col elem q8*8
    // bg (per cc): row cc*8 + r8 in Gt (stride 72), col elem mh*32 + q8*8
    int r8 = lane & 7, q8 = lane >> 3;
    uint32_t bpoff = (uint32_t)(((mh * 32 + r8) * 40 + q8 * 8) * 2);
    uint32_t bgoff = (uint32_t)((r8 * 72 + mh * 32 + q8 * 8) * 2);

    auto issue = [&](int mt, int bufi) {
        const bf16* ps = phB + (size_t)mt * 64 * CI;
        const bf16* gs = gB + mt * 64;
        {   // phi: 64 rows x 32 ci
            int r = tid >> 2, q = tid & 3;
            cp16(&Ph[bufi][r * 40 + q * 8], ps + (size_t)r * CI + q * 8);
        }
        {   // g: 32 rows x 64 m
            int r = tid >> 3, q = tid & 7;
            cp16(&Gt[bufi][r * 72 + q * 8], gs + (size_t)r * N_ + q * 8);
        }
    };

    issue(0, 0);
    CP_COMMIT;
    for (int mt = 0; mt < 32; ++mt) {
        CP_WAIT0;
        __syncthreads();
        if (mt + 1 < 32) { issue(mt + 1, (mt + 1) & 1); CP_COMMIT; }
        int bufi = mt & 1;
        uint32_t phbase = smem_u32(Ph[bufi]) + bpoff;
        uint32_t ap[2][4];
#pragma unroll
        for (int j = 0; j < 4; j++) {
            uint32_t bp[4];  // {kk0 klo, kk0 khi, kk1 klo, kk1 khi}
            ldsm_x4(bp, phbase + j * (8 * 40 * 2));
            float c[4] = {0.f, 0.f, 0.f, 0.f};
            mma16816(c, a[0], bp);
            mma16816(c, a[1], bp + 2);
            float2 cvp = *(const float2*)&cvA[mt * 64 + mh * 32 + j * 8 + tg * 2];
            float p0 = ex2f(c[0]) * cvp.x;
            float p1 = ex2f(c[1]) * cvp.y;
            float p2 = ex2f(c[2]) * cvp.x;
            float p3 = ex2f(c[3]) * cvp.y;
            int kt = j >> 1;
            int o = (j & 1) ? 2 : 0;
            ap[kt][o] = pack_bf2(p0, p1);
            ap[kt][o + 1] = pack_bf2(p2, p3);
        }
        uint32_t gtbase = smem_u32(Gt[bufi]) + bgoff;
#pragma unroll
        for (int cc = 0; cc < 4; cc++) {
            uint32_t bg[4];  // {kt0 klo, kt0 khi, kt1 klo, kt1 khi}
            ldsm_x4(bg, gtbase + cc * (8 * 72 * 2));
            mma16816(x1[cc], ap[0], bg);
            mma16816(x1[cc], ap[1], bg + 2);
        }
    }

    // in-block mh reduce (xr aliases dead Ph tiles)
    __syncthreads();
    if (mh == 1) {
        float* dst = xr + (wq * 32 + lane) * 17;
#pragma unroll
        for (int cc = 0; cc < 4; cc++)
#pragma unroll
            for (int k = 0; k < 4; k++) dst[cc * 4 + k] = x1[cc][k];
    }
    __syncthreads();
    if (mh == 0) {
        const float* src = xr + (wq * 32 + lane) * 17;
#pragma unroll
        for (int cc = 0; cc < 4; cc++)
#pragma unroll
            for (int k = 0; k < 4; k++) x1[cc][k] += src[cc * 4 + k];

        // W-conv epilogue on this half's x1, RED into zout
        uint32_t ax[2][4];
#pragma unroll
        for (int cc = 0; cc < 4; cc++) {
            int kt = cc >> 1;
            int o = (cc & 1) ? 2 : 0;
            ax[kt][o] = pack_bf2(x1[cc][0], x1[cc][1]);
            ax[kt][o + 1] = pack_bf2(x1[cc][2], x1[cc][3]);
        }
#pragma unroll
        for (int cc2 = 0; cc2 < 8; cc2++) {
            float zc[4] = {0.f, 0.f, 0.f, 0.f};
#pragma unroll
            for (int kk = 0; kk < 2; kk++) {
                uint32_t bw[2];
                const bf16* p = Ws + (cc2 * 8 + g) * 40 + kk * 16 + tg * 2;
                bw[0] = *(const uint32_t*)p;
                bw[1] = *(const uint32_t*)(p + 8);
                mma16816(zc, ax[kk], bw);
            }
            int c = cc2 * 8 + tg * 2;
            int n = n0 + wq * 16 + g;
            size_t base = ((size_t)b * C_ + c) * N_ + n;
            atomicAdd(&zout[base], zc[0]);
            atomicAdd(&zout[base + N_], zc[1]);
            atomicAdd(&zout[base + 8], zc[2]);
            atomicAdd(&zout[base + N_ + 8], zc[3]);
        }
    }
}

extern "C" void kernel_launch(void* const* d_in, const int* in_sizes, int n_in,
                              void* d_out, int out_size) {
    const float* supp = (const float*)d_in[0];
    const float* ref = (const float*)d_in[1];
    const float* tw = (const float*)d_in[2];
    const float* tb = (const float*)d_in[3];
    const float* pw = (const float*)d_in[4];
    const float* pb = (const float*)d_in[5];
    const float* gw = (const float*)d_in[6];
    const float* gb = (const float*)d_in[7];
    const float* ww = (const float*)d_in[8];
    const float* wb = (const float*)d_in[9];
    float* z = (float*)d_out;

    prep_kernel<<<dim3(N_ / 256, B_, 6), 256>>>(supp, ref, tw, tb, pw, pb, gw, gb);
    init_kernel<<<512, 256>>>(supp, wb, z);
    pass1_kernel<<<dim3(N_ / 64, B_, 2), 256>>>();
    pass2_kernel<<<dim3(N_ / 64, B_, 2), 256>>>(ww, z);
}